// round 2
// baseline (speedup 1.0000x reference)
#include <cuda_runtime.h>
#include <cuda_bf16.h>

// Fused DynamicPointConvBackBone:
//   out rows = only the B*K resampled rows (offsets[b]+j, j<min(num_list[b],K))
//   per row: gather 27 neighbor feature rows (C_in=64) -> [1,1728] @ W[1728,128]
//            -> LayerNorm(eps=1e-3) -> *gamma +beta -> ReLU
//   plus coords output [B*K, 4] = [batch-quirk col, xyz]
//
// Output layout (float32): [rows_total*C_out] features, then [rows_total*4] coords.
// NOTE: voxel_idx is int32 on the wire (JAX x64 disabled downcasts int64->int32).

#define TILE_R 64
#define KT 32
#define NTHREADS 256
#define MAXK3 32

__global__ __launch_bounds__(NTHREADS, 2)
void fused_block_kernel(
    const float* __restrict__ feat,        // [N, Cin]
    const int* __restrict__ vidx,          // [M, K3]  (int32!)
    const int* __restrict__ num_list,      // [B]
    const float* __restrict__ W,           // [K3*Cin, 128]
    const float* __restrict__ gamma,       // [128]
    const float* __restrict__ beta,        // [128]
    float* __restrict__ out_feat,          // [rows_total, 128]
    int N, int M, int K3, int Cin, int B, int K, int rows_total)
{
    __shared__ float s_a[KT][TILE_R + 1];       // A^T tile: [k][row], pitch 65
    __shared__ float s_b[KT][128];              // W tile:  [k][col]
    __shared__ int   s_idx[TILE_R * MAXK3];     // clipped neighbor idx (-1 => padding)
    __shared__ int   s_src[TILE_R];
    __shared__ unsigned char s_valid[TILE_R];

    const int tid  = threadIdx.x;
    const int row0 = blockIdx.x * TILE_R;

    // ---- per-row source index / validity ----
    if (tid < TILE_R) {
        int r = row0 + tid;
        int src = 0;
        bool valid = false;
        if (r < rows_total) {
            int b = r / K;
            int j = r - b * K;
            int off = 0;
            for (int i = 0; i < b; ++i) off += num_list[i];
            int nb  = num_list[b];
            valid   = j < min(nb, K);
            src     = off + j;
            src     = max(0, min(src, M - 1));
        }
        s_src[tid]   = src;
        s_valid[tid] = valid ? 1 : 0;
    }
    __syncthreads();

    // ---- preload all neighbor indices for this row tile ----
    for (int i = tid; i < TILE_R * K3; i += NTHREADS) {
        int rr = i / K3;
        int kk = i - rr * K3;
        int v = vidx[(long long)s_src[rr] * K3 + kk];
        int iv;
        if (v < 0)        iv = -1;                  // padding -> 0.0
        else if (v >= N)  iv = N - 1;               // clip
        else              iv = v;
        s_idx[rr * MAXK3 + kk] = iv;
    }
    // consumed after the first __syncthreads() inside the main loop

    const int ty = tid >> 4;   // 0..15 -> rows ty*4..ty*4+3
    const int tx = tid & 15;   // 0..15 -> cols tx*8..tx*8+7

    float acc[4][8];
    #pragma unroll
    for (int i = 0; i < 4; ++i)
        #pragma unroll
        for (int j = 0; j < 8; ++j) acc[i][j] = 0.f;

    const int Ktot = K3 * Cin;        // 1728
    const int nkt  = Ktot / KT;       // 54

    for (int kt = 0; kt < nkt; ++kt) {
        __syncthreads();   // previous compute done (and s_idx/s_src ready on kt=0)

        const int kbase = kt * KT;
        // ---- load A tile (gathered, transposed into smem) ----
        {
            const int ci   = tid & 31;            // k within tile
            const int kcol = kbase + ci;
            const int k3   = kcol / Cin;
            const int cin  = kcol - k3 * Cin;
            #pragma unroll
            for (int rr = tid >> 5; rr < TILE_R; rr += 8) {
                int gi = s_idx[rr * MAXK3 + k3];
                float v = 0.f;
                if (gi >= 0) v = feat[(long long)gi * Cin + cin];
                s_a[ci][rr] = v;
            }
        }
        // ---- load B tile (W rows kbase..kbase+31, 128 cols) ----
        {
            const float4* W4  = (const float4*)(W + (long long)kbase * 128);
            float4*       sb4 = (float4*)(&s_b[0][0]);
            const int c4 = tid & 31;
            #pragma unroll
            for (int kr = tid >> 5; kr < KT; kr += 8) {
                sb4[kr * 32 + c4] = W4[kr * 32 + c4];
            }
        }
        __syncthreads();

        // ---- compute ----
        #pragma unroll 8
        for (int kk = 0; kk < KT; ++kk) {
            float a0 = s_a[kk][ty * 4 + 0];
            float a1 = s_a[kk][ty * 4 + 1];
            float a2 = s_a[kk][ty * 4 + 2];
            float a3 = s_a[kk][ty * 4 + 3];
            float4 b0 = *(const float4*)&s_b[kk][tx * 8];
            float4 b1 = *(const float4*)&s_b[kk][tx * 8 + 4];
            acc[0][0] = fmaf(a0, b0.x, acc[0][0]);
            acc[0][1] = fmaf(a0, b0.y, acc[0][1]);
            acc[0][2] = fmaf(a0, b0.z, acc[0][2]);
            acc[0][3] = fmaf(a0, b0.w, acc[0][3]);
            acc[0][4] = fmaf(a0, b1.x, acc[0][4]);
            acc[0][5] = fmaf(a0, b1.y, acc[0][5]);
            acc[0][6] = fmaf(a0, b1.z, acc[0][6]);
            acc[0][7] = fmaf(a0, b1.w, acc[0][7]);
            acc[1][0] = fmaf(a1, b0.x, acc[1][0]);
            acc[1][1] = fmaf(a1, b0.y, acc[1][1]);
            acc[1][2] = fmaf(a1, b0.z, acc[1][2]);
            acc[1][3] = fmaf(a1, b0.w, acc[1][3]);
            acc[1][4] = fmaf(a1, b1.x, acc[1][4]);
            acc[1][5] = fmaf(a1, b1.y, acc[1][5]);
            acc[1][6] = fmaf(a1, b1.z, acc[1][6]);
            acc[1][7] = fmaf(a1, b1.w, acc[1][7]);
            acc[2][0] = fmaf(a2, b0.x, acc[2][0]);
            acc[2][1] = fmaf(a2, b0.y, acc[2][1]);
            acc[2][2] = fmaf(a2, b0.z, acc[2][2]);
            acc[2][3] = fmaf(a2, b0.w, acc[2][3]);
            acc[2][4] = fmaf(a2, b1.x, acc[2][4]);
            acc[2][5] = fmaf(a2, b1.y, acc[2][5]);
            acc[2][6] = fmaf(a2, b1.z, acc[2][6]);
            acc[2][7] = fmaf(a2, b1.w, acc[2][7]);
            acc[3][0] = fmaf(a3, b0.x, acc[3][0]);
            acc[3][1] = fmaf(a3, b0.y, acc[3][1]);
            acc[3][2] = fmaf(a3, b0.z, acc[3][2]);
            acc[3][3] = fmaf(a3, b0.w, acc[3][3]);
            acc[3][4] = fmaf(a3, b1.x, acc[3][4]);
            acc[3][5] = fmaf(a3, b1.y, acc[3][5]);
            acc[3][6] = fmaf(a3, b1.z, acc[3][6]);
            acc[3][7] = fmaf(a3, b1.w, acc[3][7]);
        }
    }

    // ---- epilogue: LayerNorm over 128 cols (16 threads share one row) ----
    const float invC = 1.0f / 128.0f;
    #pragma unroll
    for (int i = 0; i < 4; ++i) {
        const int rr = ty * 4 + i;
        float s = 0.f, s2 = 0.f;
        #pragma unroll
        for (int j = 0; j < 8; ++j) { s += acc[i][j]; s2 += acc[i][j] * acc[i][j]; }
        #pragma unroll
        for (int m = 8; m >= 1; m >>= 1) {
            s  += __shfl_xor_sync(0xffffffffu, s,  m);
            s2 += __shfl_xor_sync(0xffffffffu, s2, m);
        }
        float mu  = s * invC;
        float var = fmaxf(s2 * invC - mu * mu, 0.f);
        float inv = rsqrtf(var + 1e-3f);

        int r = row0 + rr;
        if (r < rows_total) {
            bool valid = (s_valid[rr] != 0);
            float* o = out_feat + (long long)r * 128 + tx * 8;
            #pragma unroll
            for (int j = 0; j < 8; ++j) {
                float v = 0.f;
                if (valid) {
                    int c = tx * 8 + j;
                    v = (acc[i][j] - mu) * inv * gamma[c] + beta[c];
                    v = fmaxf(v, 0.f);
                }
                o[j] = v;
            }
        }
    }
}

__global__ void coords_kernel(
    const float* __restrict__ coors,     // [M, 3]
    const int* __restrict__ num_list,    // [B]
    float* __restrict__ out_coor,        // [rows_total, 4]
    int M, int B, int K, int rows_total)
{
    int r = blockIdx.x * blockDim.x + threadIdx.x;
    if (r >= rows_total) return;
    int b = r / K;
    int j = r - b * K;
    int off = 0;
    for (int i = 0; i < b; ++i) off += num_list[i];
    bool valid = j < min(num_list[b], K);
    int src = max(0, min(off + j, M - 1));
    float col0 = (b < B - 1) ? (float)(b + 1) : 0.f;
    float x = 0.f, y = 0.f, z = 0.f;
    if (valid) {
        x = coors[src * 3 + 0];
        y = coors[src * 3 + 1];
        z = coors[src * 3 + 2];
    }
    float4 v = make_float4(col0, x, y, z);
    ((float4*)out_coor)[r] = v;
}

extern "C" void kernel_launch(void* const* d_in, const int* in_sizes, int n_in,
                              void* d_out, int out_size) {
    const float* feat     = (const float*)d_in[0];
    const float* coors    = (const float*)d_in[1];
    const int*   vidx     = (const int*)d_in[2];      // int32 on the wire
    const int*   num_list = (const int*)d_in[3];
    const float* W        = (const float*)d_in[4];
    const float* gamma    = (const float*)d_in[5];
    const float* beta     = (const float*)d_in[6];

    int B    = in_sizes[3];
    int Cout = in_sizes[5];                 // 128
    int M    = in_sizes[1] / 3;
    int K3   = in_sizes[2] / M;             // 27
    int Cin  = (in_sizes[4] / Cout) / K3;   // 64
    int N    = in_sizes[0] / Cin;

    int rows_total = out_size / (Cout + 4); // B*K
    int K = rows_total / B;

    float* out_feat = (float*)d_out;
    float* out_coor = out_feat + (size_t)rows_total * Cout;

    int grid = (rows_total + TILE_R - 1) / TILE_R;
    fused_block_kernel<<<grid, NTHREADS>>>(feat, vidx, num_list, W, gamma, beta,
                                           out_feat, N, M, K3, Cin, B, K, rows_total);

    int cg = (rows_total + 255) / 256;
    coords_kernel<<<cg, 256>>>(coors, num_list, out_coor, M, B, K, rows_total);
}

// round 4
// speedup vs baseline: 1.4176x; 1.4176x over previous
#include <cuda_runtime.h>
#include <cuda_bf16.h>

// Fused DynamicPointConvBackBone (resample-first):
//   only the B*K resampled rows are computed.
//   per row: gather 27 neighbor feature rows (C_in=64) -> [1,1728] @ W[1728,128]
//            -> LayerNorm(eps=1e-3) -> *gamma +beta -> ReLU ; plus coords [B*K,4].
// voxel_idx is int32 on the wire (JAX x64 disabled).
// R3: fma.rn.f32x2 packed FMAs, double-buffered smem (1 barrier/k-tile),
//     register prefetch of next tile, coords fused into main kernel.

#define TILE_R 64
#define KT 32
#define NTHREADS 256
#define MAXK3 32
#define APITCH 66   // even pitch -> 8B-aligned float2 row-pair loads

__device__ __forceinline__ unsigned long long pack2(float x) {
    unsigned long long r;
    asm("mov.b64 %0, {%1, %1};" : "=l"(r) : "f"(x));
    return r;
}
__device__ __forceinline__ void fma2(unsigned long long& acc,
                                     unsigned long long a, unsigned long long b) {
    asm("fma.rn.f32x2 %0, %1, %2, %0;" : "+l"(acc) : "l"(a), "l"(b));
}
__device__ __forceinline__ float2 unpack2(unsigned long long v) {
    float2 f;
    asm("mov.b64 {%0, %1}, %2;" : "=f"(f.x), "=f"(f.y) : "l"(v));
    return f;
}

__global__ __launch_bounds__(NTHREADS, 1)
void fused_block_kernel(
    const float* __restrict__ feat,        // [N, Cin]
    const float* __restrict__ coors,       // [M, 3]
    const int* __restrict__ vidx,          // [M, K3] int32
    const int* __restrict__ num_list,      // [B]
    const float* __restrict__ W,           // [K3*Cin, 128]
    const float* __restrict__ gamma,       // [128]
    const float* __restrict__ beta,        // [128]
    float* __restrict__ out_feat,          // [rows_total, 128]
    float* __restrict__ out_coor,          // [rows_total, 4]
    int N, int M, int K3, int Cin, int B, int K, int rows_total)
{
    __shared__ float s_a[2][KT][APITCH];    // A^T: [buf][k][row]
    __shared__ float s_b[2][KT][128];       // W:   [buf][k][col]
    __shared__ int   s_idx[TILE_R * MAXK3]; // clipped neighbor idx (-1 => pad)
    __shared__ int   s_src[TILE_R];
    __shared__ unsigned char s_valid[TILE_R];

    const int tid  = threadIdx.x;
    const int row0 = blockIdx.x * TILE_R;
    const int lane = tid & 31;
    const int wrp  = tid >> 5;

    // ---- per-row source index / validity ----
    if (tid < TILE_R) {
        int r = row0 + tid;
        int src = 0; bool valid = false;
        if (r < rows_total) {
            int b = r / K;
            int j = r - b * K;
            int off = 0;
            for (int i = 0; i < b; ++i) off += num_list[i];
            valid = j < min(num_list[b], K);
            src   = max(0, min(off + j, M - 1));
        }
        s_src[tid] = src;
        s_valid[tid] = valid ? 1 : 0;
    }
    __syncthreads();

    // ---- preload neighbor indices for this row tile ----
    for (int i = tid; i < TILE_R * K3; i += NTHREADS) {
        int rr = i / K3;
        int kk = i - rr * K3;
        int v  = vidx[(long long)s_src[rr] * K3 + kk];
        s_idx[rr * MAXK3 + kk] = (v < 0) ? -1 : min(v, N - 1);
    }
    __syncthreads();

    const int Ktot = K3 * Cin;     // 1728
    const int nkt  = Ktot / KT;    // 54

    float  pa[8];
    float4 pb[4];

    auto load_tile = [&](int kt) {
        const int kbase = kt * KT;
        const int kcol  = kbase + lane;
        const int k3    = kcol / Cin;          // uniform across lanes (32 | kbase)
        const int cin   = kcol - k3 * Cin;
        #pragma unroll
        for (int i = 0; i < 8; ++i) {
            int rr = wrp + i * 8;
            int gi = s_idx[rr * MAXK3 + k3];
            pa[i] = (gi >= 0) ? __ldg(feat + (long long)gi * Cin + cin) : 0.f;
        }
        const float4* W4 = (const float4*)(W + (long long)kbase * 128);
        #pragma unroll
        for (int i = 0; i < 4; ++i)
            pb[i] = W4[(wrp + i * 8) * 32 + lane];
    };
    auto store_tile = [&](int buf) {
        #pragma unroll
        for (int i = 0; i < 8; ++i)
            s_a[buf][lane][wrp + i * 8] = pa[i];
        #pragma unroll
        for (int i = 0; i < 4; ++i)
            *(float4*)&s_b[buf][wrp + i * 8][lane * 4] = pb[i];
    };

    const int ty = tid >> 4;   // 0..15 -> rows ty*4..+3
    const int tx = tid & 15;   // 0..15 -> cols tx*8..+7

    unsigned long long acc2[4][4];
    #pragma unroll
    for (int i = 0; i < 4; ++i)
        #pragma unroll
        for (int p = 0; p < 4; ++p) acc2[i][p] = 0ull;

    // prologue
    load_tile(0);
    store_tile(0);
    __syncthreads();

    for (int kt = 0; kt < nkt; ++kt) {
        const int cur = kt & 1;
        const bool have_next = (kt + 1) < nkt;
        if (have_next) load_tile(kt + 1);

        const float* sa = &s_a[cur][0][0];
        const float* sb = &s_b[cur][0][0];
        #pragma unroll 8
        for (int kk = 0; kk < KT; ++kk) {
            float2 a01 = *(const float2*)(sa + kk * APITCH + ty * 4);
            float2 a23 = *(const float2*)(sa + kk * APITCH + ty * 4 + 2);
            ulonglong2 bb0 = *(const ulonglong2*)(sb + kk * 128 + tx * 8);
            ulonglong2 bb1 = *(const ulonglong2*)(sb + kk * 128 + tx * 8 + 4);
            unsigned long long aa;
            aa = pack2(a01.x);
            fma2(acc2[0][0], aa, bb0.x); fma2(acc2[0][1], aa, bb0.y);
            fma2(acc2[0][2], aa, bb1.x); fma2(acc2[0][3], aa, bb1.y);
            aa = pack2(a01.y);
            fma2(acc2[1][0], aa, bb0.x); fma2(acc2[1][1], aa, bb0.y);
            fma2(acc2[1][2], aa, bb1.x); fma2(acc2[1][3], aa, bb1.y);
            aa = pack2(a23.x);
            fma2(acc2[2][0], aa, bb0.x); fma2(acc2[2][1], aa, bb0.y);
            fma2(acc2[2][2], aa, bb1.x); fma2(acc2[2][3], aa, bb1.y);
            aa = pack2(a23.y);
            fma2(acc2[3][0], aa, bb0.x); fma2(acc2[3][1], aa, bb0.y);
            fma2(acc2[3][2], aa, bb1.x); fma2(acc2[3][3], aa, bb1.y);
        }

        if (have_next) store_tile(cur ^ 1);
        __syncthreads();
    }

    // ---- epilogue: LayerNorm over 128 cols (16 threads per row) ----
    float acc[4][8];
    #pragma unroll
    for (int i = 0; i < 4; ++i)
        #pragma unroll
        for (int p = 0; p < 4; ++p) {
            float2 f = unpack2(acc2[i][p]);
            acc[i][2 * p]     = f.x;
            acc[i][2 * p + 1] = f.y;
        }

    const float invC = 1.0f / 128.0f;
    #pragma unroll
    for (int i = 0; i < 4; ++i) {
        const int rr = ty * 4 + i;
        float s = 0.f, s2 = 0.f;
        #pragma unroll
        for (int j = 0; j < 8; ++j) { s += acc[i][j]; s2 += acc[i][j] * acc[i][j]; }
        #pragma unroll
        for (int m = 8; m >= 1; m >>= 1) {
            s  += __shfl_xor_sync(0xffffffffu, s,  m);
            s2 += __shfl_xor_sync(0xffffffffu, s2, m);
        }
        float mu  = s * invC;
        float var = fmaxf(s2 * invC - mu * mu, 0.f);
        float inv = rsqrtf(var + 1e-3f);

        int r = row0 + rr;
        if (r < rows_total) {
            bool valid = (s_valid[rr] != 0);
            float* o = out_feat + (long long)r * 128 + tx * 8;
            #pragma unroll
            for (int j = 0; j < 8; ++j) {
                float v = 0.f;
                if (valid) {
                    int c = tx * 8 + j;
                    v = fmaxf((acc[i][j] - mu) * inv * gamma[c] + beta[c], 0.f);
                }
                o[j] = v;
            }
        }
    }

    // ---- fused coords output ----
    if (tid < TILE_R) {
        int r = row0 + tid;
        if (r < rows_total) {
            int b = r / K;
            float col0 = (b < B - 1) ? (float)(b + 1) : 0.f;
            float x = 0.f, y = 0.f, z = 0.f;
            if (s_valid[tid]) {
                int src = s_src[tid];
                x = coors[src * 3 + 0];
                y = coors[src * 3 + 1];
                z = coors[src * 3 + 2];
            }
            ((float4*)out_coor)[r] = make_float4(col0, x, y, z);
        }
    }
}

extern "C" void kernel_launch(void* const* d_in, const int* in_sizes, int n_in,
                              void* d_out, int out_size) {
    const float* feat     = (const float*)d_in[0];
    const float* coors    = (const float*)d_in[1];
    const int*   vidx     = (const int*)d_in[2];
    const int*   num_list = (const int*)d_in[3];
    const float* W        = (const float*)d_in[4];
    const float* gamma    = (const float*)d_in[5];
    const float* beta     = (const float*)d_in[6];

    int B    = in_sizes[3];
    int Cout = in_sizes[5];                 // 128
    int M    = in_sizes[1] / 3;
    int K3   = in_sizes[2] / M;             // 27
    int Cin  = (in_sizes[4] / Cout) / K3;   // 64
    int N    = in_sizes[0] / Cin;

    int rows_total = out_size / (Cout + 4); // B*K
    int K = rows_total / B;

    float* out_feat = (float*)d_out;
    float* out_coor = out_feat + (size_t)rows_total * Cout;

    int grid = (rows_total + TILE_R - 1) / TILE_R;
    fused_block_kernel<<<grid, NTHREADS>>>(feat, coors, vidx, num_list, W, gamma, beta,
                                           out_feat, out_coor,
                                           N, M, K3, Cin, B, K, rows_total);
}

// round 6
// speedup vs baseline: 4.6327x; 3.2680x over previous
#include <cuda_runtime.h>
#include <cuda_bf16.h>
#include <cstdint>

// DynamicPointConvBackBone via mma.sync (base-ISA HMMA path; tcgen05 is not
// available on the harness's compute_103 PTX target).
// Resample-first: only B*K rows computed. GEMM [8192 x 1728] @ [1728 x 128]
// as bf16 split (ah*bh + ah*bl + al*bh) accumulated in fp32, then
// LayerNorm(eps=1e-3)+ReLU epilogue, plus coords output.
// voxel_idx is int32 on the wire.

#define TILE_M 64
#define NTH    256
#define IDXP   28
#define MAXCH  28
#define CHUNK  64        // = Cin
#define ATB    8192      // A tile bytes (64 rows x 64 bf16 x 2B)
#define BTB    16384     // B tile bytes (64 k x 128 n x 2B)

// dynamic smem layout (16B-aligned blocks)
#define SM_AH  0
#define SM_AL  (SM_AH + 2 * ATB)      // 16384
#define SM_BH  (SM_AL + 2 * ATB)      // 32768
#define SM_BL  (SM_BH + 2 * BTB)      // 65536
#define SM_IDX (SM_BL + 2 * BTB)      // 98304
#define SM_SRC (SM_IDX + TILE_M * IDXP * 4)  // 105472
#define SM_VAL (SM_SRC + TILE_M * 4)         // 105728
#define SM_RED (SM_VAL + 64)                 // 105792  (64 rows x 4 floats)
#define SM_GB  (SM_RED + TILE_M * 4 * 4)     // 106816  (gamma 128 + beta 128)
#define SM_TOTAL (SM_GB + 256 * 4)           // 107840

__device__ __nv_bfloat16 g_wh[MAXCH * CHUNK * 128];   // [k][n] bf16 hi
__device__ __nv_bfloat16 g_wl[MAXCH * CHUNK * 128];   // [k][n] bf16 lo

static __device__ __forceinline__ uint32_t smem_u32(const void* p) {
    uint32_t a;
    asm("{ .reg .u64 t; cvta.to.shared.u64 t, %1; cvt.u32.u64 %0, t; }" : "=r"(a) : "l"(p));
    return a;
}
static __device__ __forceinline__ uint32_t pack_bf(float lo, float hi) {
    uint32_t r;
    asm("cvt.rn.bf16x2.f32 %0, %1, %2;" : "=r"(r) : "f"(hi), "f"(lo));
    return r;
}
static __device__ __forceinline__ void cpasync16(uint32_t dst, const void* src) {
    asm volatile("cp.async.cg.shared.global [%0], [%1], 16;" :: "r"(dst), "l"(src) : "memory");
}
static __device__ __forceinline__ void cpwait_all() {
    asm volatile("cp.async.wait_all;" ::: "memory");
}
static __device__ __forceinline__ void ldsm4(uint32_t* r, uint32_t addr) {
    asm volatile("ldmatrix.sync.aligned.m8n8.x4.shared.b16 {%0,%1,%2,%3}, [%4];"
                 : "=r"(r[0]), "=r"(r[1]), "=r"(r[2]), "=r"(r[3]) : "r"(addr));
}
static __device__ __forceinline__ void ldsm4t(uint32_t* r, uint32_t addr) {
    asm volatile("ldmatrix.sync.aligned.m8n8.x4.trans.shared.b16 {%0,%1,%2,%3}, [%4];"
                 : "=r"(r[0]), "=r"(r[1]), "=r"(r[2]), "=r"(r[3]) : "r"(addr));
}
static __device__ __forceinline__ void mma16816(float* d, const uint32_t* a,
                                                uint32_t b0, uint32_t b1) {
    asm volatile(
        "mma.sync.aligned.m16n8k16.row.col.f32.bf16.bf16.f32 "
        "{%0,%1,%2,%3}, {%4,%5,%6,%7}, {%8,%9}, {%0,%1,%2,%3};"
        : "+f"(d[0]), "+f"(d[1]), "+f"(d[2]), "+f"(d[3])
        : "r"(a[0]), "r"(a[1]), "r"(a[2]), "r"(a[3]), "r"(b0), "r"(b1));
}

// ---------------- prep: split W into bf16 hi/lo [k][n] ----------------
__global__ void prep_w(const float* __restrict__ W, int total) {
    int idx = blockIdx.x * blockDim.x + threadIdx.x;
    if (idx >= total) return;
    float v = W[idx];
    __nv_bfloat16 h = __float2bfloat16(v);
    g_wh[idx] = h;
    g_wl[idx] = __float2bfloat16(v - __bfloat162float(h));
}

// ---------------- main fused kernel ----------------
__global__ __launch_bounds__(NTH, 1)
void fused_mma_kernel(
    const float* __restrict__ feat,   // [N, 64]
    const float* __restrict__ coors,  // [M, 3]
    const int*   __restrict__ vidx,   // [M, K3]
    const int*   __restrict__ nums,   // [B]
    const float* __restrict__ gamma,  // [128]
    const float* __restrict__ beta,   // [128]
    float* __restrict__ out_feat,     // [rows_total, 128]
    float* __restrict__ out_coor,     // [rows_total, 4]
    int N, int M, int K3, int B, int K, int rows_total)
{
    extern __shared__ __align__(128) char sm[];
    const uint32_t smb = smem_u32(sm);
    const int tid  = threadIdx.x;
    const int wid  = tid >> 5;
    const int lane = tid & 31;
    const int row0 = blockIdx.x * TILE_M;

    int* s_idx = (int*)(sm + SM_IDX);
    int* s_src = (int*)(sm + SM_SRC);
    unsigned char* s_val = (unsigned char*)(sm + SM_VAL);
    float* s_red = (float*)(sm + SM_RED);
    float* s_gb  = (float*)(sm + SM_GB);

    // per-row source & validity; gamma/beta preload
    if (tid < TILE_M) {
        int r = row0 + tid;
        int src = 0; bool valid = false;
        if (r < rows_total) {
            int b = r / K;
            int j = r - b * K;
            int off = 0;
            for (int i = 0; i < b; ++i) off += nums[i];
            valid = j < min(nums[b], K);
            src   = max(0, min(off + j, M - 1));
        }
        s_src[tid] = src;
        s_val[tid] = valid ? 1 : 0;
    }
    if (tid < 128) {
        s_gb[tid]       = gamma[tid];
        s_gb[128 + tid] = beta[tid];
    }
    __syncthreads();

    // neighbor indices for this row tile
    for (int i = tid; i < TILE_M * K3; i += NTH) {
        int rr = i / K3, cc = i - rr * K3;
        int v = vidx[(long long)s_src[rr] * K3 + cc];
        s_idx[rr * IDXP + cc] = (v < 0) ? -1 : min(v, N - 1);
    }
    __syncthreads();

    // -------- loader helpers --------
    const int arow = tid >> 2;          // gather row 0..63
    const int aseg = tid & 3;           // 64B segment of 256B feature row
    float4 pa[4];

    auto a_issue = [&](int c) {
        int gi = s_idx[arow * IDXP + c];
        if (gi >= 0) {
            const float4* src = (const float4*)(feat + (size_t)gi * CHUNK) + aseg * 4;
            pa[0] = __ldg(src + 0); pa[1] = __ldg(src + 1);
            pa[2] = __ldg(src + 2); pa[3] = __ldg(src + 3);
        } else {
            pa[0] = pa[1] = pa[2] = pa[3] = make_float4(0.f, 0.f, 0.f, 0.f);
        }
    };
    auto a_store = [&](int buf) {
        char* ah = sm + SM_AH + buf * ATB + arow * 128;
        char* al = sm + SM_AL + buf * ATB + arow * 128;
        const int sw = (arow & 7);
        #pragma unroll
        for (int u = 0; u < 2; ++u) {
            float4 v0 = pa[2 * u], v1 = pa[2 * u + 1];
            uint4 h, l;
            h.x = pack_bf(v0.x, v0.y);
            h.y = pack_bf(v0.z, v0.w);
            h.z = pack_bf(v1.x, v1.y);
            h.w = pack_bf(v1.z, v1.w);
            l.x = pack_bf(v0.x - __uint_as_float(h.x << 16), v0.y - __uint_as_float(h.x & 0xFFFF0000u));
            l.y = pack_bf(v0.z - __uint_as_float(h.y << 16), v0.w - __uint_as_float(h.y & 0xFFFF0000u));
            l.z = pack_bf(v1.x - __uint_as_float(h.z << 16), v1.w - __uint_as_float(h.z & 0xFFFF0000u));
            // fix: l.z second arg uses v1.y
            l.z = pack_bf(v1.x - __uint_as_float(h.z << 16), v1.y - __uint_as_float(h.z & 0xFFFF0000u));
            l.w = pack_bf(v1.z - __uint_as_float(h.w << 16), v1.w - __uint_as_float(h.w & 0xFFFF0000u));
            const int unit = aseg * 2 + u;
            const int o = ((unit ^ sw) << 4);
            *(uint4*)(ah + o) = h;
            *(uint4*)(al + o) = l;
        }
    };
    auto b_issue = [&](int c, int buf) {
        const char* srcH = (const char*)g_wh + (size_t)c * BTB;
        const char* srcL = (const char*)g_wl + (size_t)c * BTB;
        uint32_t dH = smb + SM_BH + buf * BTB;
        uint32_t dL = smb + SM_BL + buf * BTB;
        #pragma unroll
        for (int j = 0; j < 4; ++j) {
            int idx  = tid + j * NTH;
            int krow = idx >> 4;
            int col  = idx & 15;
            int sc   = col ^ (krow & 7);
            int so   = krow * 256 + col * 16;
            int dof  = krow * 256 + sc * 16;
            cpasync16(dH + dof, srcH + so);
            cpasync16(dL + dof, srcL + so);
        }
    };

    // -------- compute helper (per warp: m16 x n64) --------
    const int mw = wid & 3, nh = wid >> 2;
    const int m0 = mw * 16;
    float acc[8][4];
    #pragma unroll
    for (int t = 0; t < 8; ++t)
        #pragma unroll
        for (int q = 0; q < 4; ++q) acc[t][q] = 0.f;

    const int a_r   = m0 + (lane & 15);
    const int a_hi  = (lane >> 4);
    const int k_l   = (lane & 15);

    auto mma_chunk = [&](int buf) {
        const uint32_t aH = smb + SM_AH + buf * ATB + a_r * 128;
        const uint32_t aL = aH + 2 * ATB;          // SM_AL - SM_AH = 2*ATB
        const uint32_t bH = smb + SM_BH + buf * BTB;
        const uint32_t bL = bH + 2 * BTB;          // SM_BL - SM_BH = 2*BTB
        const int asw = (a_r & 7);
        #pragma unroll
        for (int ks = 0; ks < 4; ++ks) {
            uint32_t ah[4], al[4];
            const int acol = ks * 2 + a_hi;
            const uint32_t aoff = (uint32_t)((acol ^ asw) << 4);
            ldsm4(ah, aH + aoff);
            ldsm4(al, aL + aoff);
            const int krow = ks * 16 + k_l;
            const uint32_t brow = (uint32_t)(krow * 256);
            const int ksw = (krow & 7);
            #pragma unroll
            for (int tt = 0; tt < 4; ++tt) {
                uint32_t bh[4], bl[4];
                const int bcol = nh * 8 + tt * 2 + a_hi;
                const uint32_t boff = brow + (uint32_t)((bcol ^ ksw) << 4);
                ldsm4t(bh, bH + boff);
                ldsm4t(bl, bL + boff);
                mma16816(acc[2 * tt],     ah, bh[0], bh[1]);
                mma16816(acc[2 * tt + 1], ah, bh[2], bh[3]);
                mma16816(acc[2 * tt],     ah, bl[0], bl[1]);
                mma16816(acc[2 * tt + 1], ah, bl[2], bl[3]);
                mma16816(acc[2 * tt],     al, bh[0], bh[1]);
                mma16816(acc[2 * tt + 1], al, bh[2], bh[3]);
            }
        }
    };

    // -------- pipelined main loop --------
    b_issue(0, 0);
    a_issue(0);
    a_store(0);
    cpwait_all();
    __syncthreads();

    for (int c = 0; c < K3; ++c) {
        const int buf = c & 1;
        const bool nxt = (c + 1) < K3;
        if (nxt) { b_issue(c + 1, buf ^ 1); a_issue(c + 1); }
        mma_chunk(buf);
        if (nxt) a_store(buf ^ 1);
        cpwait_all();
        __syncthreads();
    }

    // -------- LayerNorm epilogue --------
    // thread owns rows r0=m0+(lane>>2), r1=r0+8; cols: slot s -> nh*64+(s>>1)*16+(s&1)*8+(lane&3)*2
    {
        float s0 = 0.f, q0 = 0.f, s1 = 0.f, q1 = 0.f;
        #pragma unroll
        for (int t = 0; t < 8; ++t) {
            s0 += acc[t][0] + acc[t][1];
            q0 += acc[t][0] * acc[t][0] + acc[t][1] * acc[t][1];
            s1 += acc[t][2] + acc[t][3];
            q1 += acc[t][2] * acc[t][2] + acc[t][3] * acc[t][3];
        }
        #pragma unroll
        for (int m = 1; m <= 2; m <<= 1) {
            s0 += __shfl_xor_sync(0xffffffffu, s0, m);
            q0 += __shfl_xor_sync(0xffffffffu, q0, m);
            s1 += __shfl_xor_sync(0xffffffffu, s1, m);
            q1 += __shfl_xor_sync(0xffffffffu, q1, m);
        }
        if ((lane & 3) == 0) {
            int r0 = m0 + (lane >> 2);
            s_red[r0 * 4 + nh * 2 + 0] = s0;
            s_red[r0 * 4 + nh * 2 + 1] = q0;
            s_red[(r0 + 8) * 4 + nh * 2 + 0] = s1;
            s_red[(r0 + 8) * 4 + nh * 2 + 1] = q1;
        }
    }
    __syncthreads();

    {
        const int r0 = m0 + (lane >> 2);
        const int r1 = r0 + 8;
        const float invC = 1.0f / 128.0f;
        float sA = s_red[r0 * 4 + 0] + s_red[r0 * 4 + 2];
        float qA = s_red[r0 * 4 + 1] + s_red[r0 * 4 + 3];
        float sB = s_red[r1 * 4 + 0] + s_red[r1 * 4 + 2];
        float qB = s_red[r1 * 4 + 1] + s_red[r1 * 4 + 3];
        float muA = sA * invC, muB = sB * invC;
        float ivA = rsqrtf(fmaxf(qA * invC - muA * muA, 0.f) + 1e-3f);
        float ivB = rsqrtf(fmaxf(qB * invC - muB * muB, 0.f) + 1e-3f);
        const int gr0 = row0 + r0, gr1 = row0 + r1;
        const bool vA = (gr0 < rows_total) && s_val[r0];
        const bool vB = (gr1 < rows_total) && s_val[r1];
        #pragma unroll
        for (int t = 0; t < 8; ++t) {
            const int c = nh * 64 + (t >> 1) * 16 + (t & 1) * 8 + (lane & 3) * 2;
            const float g0 = s_gb[c], g1 = s_gb[c + 1];
            const float b0 = s_gb[128 + c], b1 = s_gb[128 + c + 1];
            if (gr0 < rows_total) {
                float2 o = make_float2(0.f, 0.f);
                if (vA) {
                    o.x = fmaxf((acc[t][0] - muA) * ivA * g0 + b0, 0.f);
                    o.y = fmaxf((acc[t][1] - muA) * ivA * g1 + b1, 0.f);
                }
                *(float2*)(out_feat + (size_t)gr0 * 128 + c) = o;
            }
            if (gr1 < rows_total) {
                float2 o = make_float2(0.f, 0.f);
                if (vB) {
                    o.x = fmaxf((acc[t][2] - muB) * ivB * g0 + b0, 0.f);
                    o.y = fmaxf((acc[t][3] - muB) * ivB * g1 + b1, 0.f);
                }
                *(float2*)(out_feat + (size_t)gr1 * 128 + c) = o;
            }
        }
    }

    // -------- coords --------
    if (tid < TILE_M) {
        int r = row0 + tid;
        if (r < rows_total) {
            int b = r / K;
            float col0 = (b < B - 1) ? (float)(b + 1) : 0.f;
            float x = 0.f, y = 0.f, z = 0.f;
            if (s_val[tid]) {
                int src = s_src[tid];
                x = coors[src * 3 + 0];
                y = coors[src * 3 + 1];
                z = coors[src * 3 + 2];
            }
            ((float4*)out_coor)[r] = make_float4(col0, x, y, z);
        }
    }
}

extern "C" void kernel_launch(void* const* d_in, const int* in_sizes, int n_in,
                              void* d_out, int out_size) {
    const float* feat     = (const float*)d_in[0];
    const float* coors    = (const float*)d_in[1];
    const int*   vidx     = (const int*)d_in[2];
    const int*   num_list = (const int*)d_in[3];
    const float* W        = (const float*)d_in[4];
    const float* gamma    = (const float*)d_in[5];
    const float* beta     = (const float*)d_in[6];

    int B    = in_sizes[3];
    int Cout = in_sizes[5];                 // 128
    int M    = in_sizes[1] / 3;
    int K3   = in_sizes[2] / M;             // 27
    int Cin  = (in_sizes[4] / Cout) / K3;   // 64
    int N    = in_sizes[0] / Cin;
    int Ktot = K3 * Cin;

    int rows_total = out_size / (Cout + 4); // B*K
    int K = rows_total / B;

    float* out_feat = (float*)d_out;
    float* out_coor = out_feat + (size_t)rows_total * Cout;

    prep_w<<<(Ktot * Cout + 255) / 256, 256>>>(W, Ktot * Cout);

    cudaFuncSetAttribute(fused_mma_kernel,
                         cudaFuncAttributeMaxDynamicSharedMemorySize, SM_TOTAL);
    int grid = (rows_total + TILE_M - 1) / TILE_M;
    fused_mma_kernel<<<grid, NTH, SM_TOTAL>>>(feat, coors, vidx, num_list, gamma, beta,
                                              out_feat, out_coor,
                                              N, M, K3, B, K, rows_total);
}

// round 7
// speedup vs baseline: 4.8352x; 1.0437x over previous
#include <cuda_runtime.h>
#include <cuda_bf16.h>
#include <cstdint>

// DynamicPointConvBackBone via mma.sync (base-ISA HMMA; tcgen05 unavailable on
// the harness's compute_103 PTX target).
// Resample-first: only B*K rows computed. GEMM [8192 x 1728] @ [1728 x 128]
// as bf16 split (ah*bh + ah*bl + al*bh) accumulated in fp32, then
// LayerNorm(eps=1e-3)+ReLU epilogue, plus coords output.
// R6: 512 threads (16 warps, 4/SMSP) with m16xn32 warp tiles.

#define TILE_M 64
#define NTH    512
#define IDXP   28
#define MAXCH  28
#define CHUNK  64        // = Cin
#define ATB    8192      // A tile bytes (64 rows x 64 bf16 x 2B)
#define BTB    16384     // B tile bytes (64 k x 128 n x 2B)

// dynamic smem layout
#define SM_AH  0
#define SM_AL  (SM_AH + 2 * ATB)      // 16384
#define SM_BH  (SM_AL + 2 * ATB)      // 32768
#define SM_BL  (SM_BH + 2 * BTB)      // 65536
#define SM_IDX (SM_BL + 2 * BTB)      // 98304
#define SM_SRC (SM_IDX + TILE_M * IDXP * 4)  // 105472
#define SM_VAL (SM_SRC + TILE_M * 4)         // 105728
#define SM_RED (SM_VAL + 64)                 // 105792  (64 rows x 4 nwarps x 2)
#define SM_GB  (SM_RED + TILE_M * 8 * 4)     // 107840  (gamma 128 + beta 128)
#define SM_TOTAL (SM_GB + 256 * 4)           // 108864

__device__ __align__(16) __nv_bfloat16 g_wh[MAXCH * CHUNK * 128];   // [k][n] hi
__device__ __align__(16) __nv_bfloat16 g_wl[MAXCH * CHUNK * 128];   // [k][n] lo

static __device__ __forceinline__ uint32_t smem_u32(const void* p) {
    uint32_t a;
    asm("{ .reg .u64 t; cvta.to.shared.u64 t, %1; cvt.u32.u64 %0, t; }" : "=r"(a) : "l"(p));
    return a;
}
static __device__ __forceinline__ uint32_t pack_bf(float lo, float hi) {
    uint32_t r;
    asm("cvt.rn.bf16x2.f32 %0, %1, %2;" : "=r"(r) : "f"(hi), "f"(lo));
    return r;
}
static __device__ __forceinline__ void cpasync16(uint32_t dst, const void* src) {
    asm volatile("cp.async.cg.shared.global [%0], [%1], 16;" :: "r"(dst), "l"(src) : "memory");
}
static __device__ __forceinline__ void cpwait_all() {
    asm volatile("cp.async.wait_all;" ::: "memory");
}
static __device__ __forceinline__ void ldsm4(uint32_t* r, uint32_t addr) {
    asm volatile("ldmatrix.sync.aligned.m8n8.x4.shared.b16 {%0,%1,%2,%3}, [%4];"
                 : "=r"(r[0]), "=r"(r[1]), "=r"(r[2]), "=r"(r[3]) : "r"(addr));
}
static __device__ __forceinline__ void ldsm4t(uint32_t* r, uint32_t addr) {
    asm volatile("ldmatrix.sync.aligned.m8n8.x4.trans.shared.b16 {%0,%1,%2,%3}, [%4];"
                 : "=r"(r[0]), "=r"(r[1]), "=r"(r[2]), "=r"(r[3]) : "r"(addr));
}
static __device__ __forceinline__ void mma16816(float* d, const uint32_t* a,
                                                uint32_t b0, uint32_t b1) {
    asm volatile(
        "mma.sync.aligned.m16n8k16.row.col.f32.bf16.bf16.f32 "
        "{%0,%1,%2,%3}, {%4,%5,%6,%7}, {%8,%9}, {%0,%1,%2,%3};"
        : "+f"(d[0]), "+f"(d[1]), "+f"(d[2]), "+f"(d[3])
        : "r"(a[0]), "r"(a[1]), "r"(a[2]), "r"(a[3]), "r"(b0), "r"(b1));
}

// ---------------- prep: split W into bf16 hi/lo [k][n] ----------------
__global__ void prep_w(const float* __restrict__ W, int total) {
    int idx = blockIdx.x * blockDim.x + threadIdx.x;
    if (idx >= total) return;
    float v = W[idx];
    __nv_bfloat16 h = __float2bfloat16(v);
    g_wh[idx] = h;
    g_wl[idx] = __float2bfloat16(v - __bfloat162float(h));
}

// ---------------- main fused kernel ----------------
__global__ __launch_bounds__(NTH, 1)
void fused_mma_kernel(
    const float* __restrict__ feat,   // [N, 64]
    const float* __restrict__ coors,  // [M, 3]
    const int*   __restrict__ vidx,   // [M, K3]
    const int*   __restrict__ nums,   // [B]
    const float* __restrict__ gamma,  // [128]
    const float* __restrict__ beta,   // [128]
    float* __restrict__ out_feat,     // [rows_total, 128]
    float* __restrict__ out_coor,     // [rows_total, 4]
    int N, int M, int K3, int B, int K, int rows_total)
{
    extern __shared__ __align__(128) char sm[];
    const uint32_t smb = smem_u32(sm);
    const int tid  = threadIdx.x;
    const int wid  = tid >> 5;
    const int lane = tid & 31;
    const int row0 = blockIdx.x * TILE_M;

    int* s_idx = (int*)(sm + SM_IDX);
    int* s_src = (int*)(sm + SM_SRC);
    unsigned char* s_val = (unsigned char*)(sm + SM_VAL);
    float* s_red = (float*)(sm + SM_RED);
    float* s_gb  = (float*)(sm + SM_GB);

    // per-row source & validity; gamma/beta preload
    if (tid < TILE_M) {
        int r = row0 + tid;
        int src = 0; bool valid = false;
        if (r < rows_total) {
            int b = r / K;
            int j = r - b * K;
            int off = 0;
            for (int i = 0; i < b; ++i) off += nums[i];
            valid = j < min(nums[b], K);
            src   = max(0, min(off + j, M - 1));
        }
        s_src[tid] = src;
        s_val[tid] = valid ? 1 : 0;
    }
    if (tid >= 128 && tid < 256) {
        s_gb[tid - 128]       = gamma[tid - 128];
        s_gb[tid]             = beta[tid - 128];
    }
    __syncthreads();

    // neighbor indices for this row tile
    for (int i = tid; i < TILE_M * K3; i += NTH) {
        int rr = i / K3, cc = i - rr * K3;
        int v = vidx[(long long)s_src[rr] * K3 + cc];
        s_idx[rr * IDXP + cc] = (v < 0) ? -1 : min(v, N - 1);
    }
    __syncthreads();

    // -------- loader helpers --------
    const int arow = tid >> 3;          // gather row 0..63
    const int aseg = tid & 7;           // 32B segment of 256B feature row
    float4 pa0, pa1;

    auto a_issue = [&](int c) {
        int gi = s_idx[arow * IDXP + c];
        if (gi >= 0) {
            const float4* src = (const float4*)(feat + (size_t)gi * CHUNK) + aseg * 2;
            pa0 = __ldg(src + 0);
            pa1 = __ldg(src + 1);
        } else {
            pa0 = pa1 = make_float4(0.f, 0.f, 0.f, 0.f);
        }
    };
    auto a_store = [&](int buf) {
        uint4 h, l;
        h.x = pack_bf(pa0.x, pa0.y);
        h.y = pack_bf(pa0.z, pa0.w);
        h.z = pack_bf(pa1.x, pa1.y);
        h.w = pack_bf(pa1.z, pa1.w);
        l.x = pack_bf(pa0.x - __uint_as_float(h.x << 16), pa0.y - __uint_as_float(h.x & 0xFFFF0000u));
        l.y = pack_bf(pa0.z - __uint_as_float(h.y << 16), pa0.w - __uint_as_float(h.y & 0xFFFF0000u));
        l.z = pack_bf(pa1.x - __uint_as_float(h.z << 16), pa1.y - __uint_as_float(h.z & 0xFFFF0000u));
        l.w = pack_bf(pa1.z - __uint_as_float(h.w << 16), pa1.w - __uint_as_float(h.w & 0xFFFF0000u));
        const int o = arow * 128 + ((aseg ^ (arow & 7)) << 4);
        *(uint4*)(sm + SM_AH + buf * ATB + o) = h;
        *(uint4*)(sm + SM_AL + buf * ATB + o) = l;
    };
    auto b_issue = [&](int c, int buf) {
        const char* srcH = (const char*)g_wh + (size_t)c * BTB;
        const char* srcL = (const char*)g_wl + (size_t)c * BTB;
        uint32_t dH = smb + SM_BH + buf * BTB;
        uint32_t dL = smb + SM_BL + buf * BTB;
        #pragma unroll
        for (int j = 0; j < 2; ++j) {
            int idx  = tid + j * NTH;
            int krow = idx >> 4;
            int col  = idx & 15;
            int dof  = krow * 256 + ((col ^ (krow & 7)) << 4);
            int so   = krow * 256 + col * 16;
            cpasync16(dH + dof, srcH + so);
            cpasync16(dL + dof, srcL + so);
        }
    };

    // -------- compute (per warp: m16 x n32) --------
    const int mw = wid & 3, nw = wid >> 2;
    const int m0 = mw * 16;
    float acc[4][4];
    #pragma unroll
    for (int t = 0; t < 4; ++t)
        #pragma unroll
        for (int q = 0; q < 4; ++q) acc[t][q] = 0.f;

    const int a_r  = m0 + (lane & 15);
    const int a_hi = (lane >> 4);
    const int k_l  = (lane & 15);

    auto mma_chunk = [&](int buf) {
        const uint32_t aH = smb + SM_AH + buf * ATB + a_r * 128;
        const uint32_t aL = aH + 2 * ATB;
        const uint32_t bH = smb + SM_BH + buf * BTB;
        const uint32_t bL = bH + 2 * BTB;
        const int asw = (a_r & 7);
        #pragma unroll
        for (int ks = 0; ks < 4; ++ks) {
            uint32_t ah[4], al[4];
            const int acol = ks * 2 + a_hi;
            const uint32_t aoff = (uint32_t)((acol ^ asw) << 4);
            ldsm4(ah, aH + aoff);
            ldsm4(al, aL + aoff);
            const int krow = ks * 16 + k_l;
            const uint32_t brow = (uint32_t)(krow * 256);
            const int ksw = (krow & 7);
            #pragma unroll
            for (int tt = 0; tt < 2; ++tt) {
                uint32_t bh[4], bl[4];
                const int bcol = nw * 4 + tt * 2 + a_hi;
                const uint32_t boff = brow + (uint32_t)((bcol ^ ksw) << 4);
                ldsm4t(bh, bH + boff);
                ldsm4t(bl, bL + boff);
                mma16816(acc[2 * tt],     ah, bh[0], bh[1]);
                mma16816(acc[2 * tt + 1], ah, bh[2], bh[3]);
                mma16816(acc[2 * tt],     ah, bl[0], bl[1]);
                mma16816(acc[2 * tt + 1], ah, bl[2], bl[3]);
                mma16816(acc[2 * tt],     al, bh[0], bh[1]);
                mma16816(acc[2 * tt + 1], al, bh[2], bh[3]);
            }
        }
    };

    // -------- pipelined main loop --------
    b_issue(0, 0);
    a_issue(0);
    a_store(0);
    cpwait_all();
    __syncthreads();

    for (int c = 0; c < K3; ++c) {
        const int buf = c & 1;
        const bool nxt = (c + 1) < K3;
        if (nxt) { b_issue(c + 1, buf ^ 1); a_issue(c + 1); }
        mma_chunk(buf);
        if (nxt) a_store(buf ^ 1);
        cpwait_all();
        __syncthreads();
    }

    // -------- LayerNorm epilogue --------
    // thread rows r0 = m0+(lane>>2), r1 = r0+8
    // tile t = tt*2+j: cols = nw*32 + tt*16 + j*8 + (lane&3)*2
    {
        float s0 = 0.f, q0 = 0.f, s1 = 0.f, q1 = 0.f;
        #pragma unroll
        for (int t = 0; t < 4; ++t) {
            s0 += acc[t][0] + acc[t][1];
            q0 += acc[t][0] * acc[t][0] + acc[t][1] * acc[t][1];
            s1 += acc[t][2] + acc[t][3];
            q1 += acc[t][2] * acc[t][2] + acc[t][3] * acc[t][3];
        }
        #pragma unroll
        for (int m = 1; m <= 2; m <<= 1) {
            s0 += __shfl_xor_sync(0xffffffffu, s0, m);
            q0 += __shfl_xor_sync(0xffffffffu, q0, m);
            s1 += __shfl_xor_sync(0xffffffffu, s1, m);
            q1 += __shfl_xor_sync(0xffffffffu, q1, m);
        }
        if ((lane & 3) == 0) {
            int r0 = m0 + (lane >> 2);
            s_red[r0 * 8 + nw * 2 + 0] = s0;
            s_red[r0 * 8 + nw * 2 + 1] = q0;
            s_red[(r0 + 8) * 8 + nw * 2 + 0] = s1;
            s_red[(r0 + 8) * 8 + nw * 2 + 1] = q1;
        }
    }
    __syncthreads();

    {
        const int r0 = m0 + (lane >> 2);
        const int r1 = r0 + 8;
        const float invC = 1.0f / 128.0f;
        float sA = s_red[r0 * 8 + 0] + s_red[r0 * 8 + 2] + s_red[r0 * 8 + 4] + s_red[r0 * 8 + 6];
        float qA = s_red[r0 * 8 + 1] + s_red[r0 * 8 + 3] + s_red[r0 * 8 + 5] + s_red[r0 * 8 + 7];
        float sB = s_red[r1 * 8 + 0] + s_red[r1 * 8 + 2] + s_red[r1 * 8 + 4] + s_red[r1 * 8 + 6];
        float qB = s_red[r1 * 8 + 1] + s_red[r1 * 8 + 3] + s_red[r1 * 8 + 5] + s_red[r1 * 8 + 7];
        float muA = sA * invC, muB = sB * invC;
        float ivA = rsqrtf(fmaxf(qA * invC - muA * muA, 0.f) + 1e-3f);
        float ivB = rsqrtf(fmaxf(qB * invC - muB * muB, 0.f) + 1e-3f);
        const int gr0 = row0 + r0, gr1 = row0 + r1;
        const bool vA = (gr0 < rows_total) && s_val[r0];
        const bool vB = (gr1 < rows_total) && s_val[r1];
        #pragma unroll
        for (int t = 0; t < 4; ++t) {
            const int c = nw * 32 + (t >> 1) * 16 + (t & 1) * 8 + (lane & 3) * 2;
            const float g0 = s_gb[c], g1 = s_gb[c + 1];
            const float b0 = s_gb[128 + c], b1 = s_gb[128 + c + 1];
            if (gr0 < rows_total) {
                float2 o = make_float2(0.f, 0.f);
                if (vA) {
                    o.x = fmaxf((acc[t][0] - muA) * ivA * g0 + b0, 0.f);
                    o.y = fmaxf((acc[t][1] - muA) * ivA * g1 + b1, 0.f);
                }
                *(float2*)(out_feat + (size_t)gr0 * 128 + c) = o;
            }
            if (gr1 < rows_total) {
                float2 o = make_float2(0.f, 0.f);
                if (vB) {
                    o.x = fmaxf((acc[t][2] - muB) * ivB * g0 + b0, 0.f);
                    o.y = fmaxf((acc[t][3] - muB) * ivB * g1 + b1, 0.f);
                }
                *(float2*)(out_feat + (size_t)gr1 * 128 + c) = o;
            }
        }
    }

    // -------- coords --------
    if (tid < TILE_M) {
        int r = row0 + tid;
        if (r < rows_total) {
            int b = r / K;
            float col0 = (b < B - 1) ? (float)(b + 1) : 0.f;
            float x = 0.f, y = 0.f, z = 0.f;
            if (s_val[tid]) {
                int src = s_src[tid];
                x = coors[src * 3 + 0];
                y = coors[src * 3 + 1];
                z = coors[src * 3 + 2];
            }
            ((float4*)out_coor)[r] = make_float4(col0, x, y, z);
        }
    }
}

extern "C" void kernel_launch(void* const* d_in, const int* in_sizes, int n_in,
                              void* d_out, int out_size) {
    const float* feat     = (const float*)d_in[0];
    const float* coors    = (const float*)d_in[1];
    const int*   vidx     = (const int*)d_in[2];
    const int*   num_list = (const int*)d_in[3];
    const float* W        = (const float*)d_in[4];
    const float* gamma    = (const float*)d_in[5];
    const float* beta     = (const float*)d_in[6];

    int B    = in_sizes[3];
    int Cout = in_sizes[5];                 // 128
    int M    = in_sizes[1] / 3;
    int K3   = in_sizes[2] / M;             // 27
    int Cin  = (in_sizes[4] / Cout) / K3;   // 64
    int N    = in_sizes[0] / Cin;
    int Ktot = K3 * Cin;

    int rows_total = out_size / (Cout + 4); // B*K
    int K = rows_total / B;

    float* out_feat = (float*)d_out;
    float* out_coor = out_feat + (size_t)rows_total * Cout;

    prep_w<<<(Ktot * Cout + 255) / 256, 256>>>(W, Ktot * Cout);

    cudaFuncSetAttribute(fused_mma_kernel,
                         cudaFuncAttributeMaxDynamicSharedMemorySize, SM_TOTAL);
    int grid = (rows_total + TILE_M - 1) / TILE_M;
    fused_mma_kernel<<<grid, NTH, SM_TOTAL>>>(feat, coors, vidx, num_list, gamma, beta,
                                              out_feat, out_coor,
                                              N, M, K3, B, K, rows_total);
}

// round 8
// speedup vs baseline: 7.3668x; 1.5236x over previous
#include <cuda_runtime.h>
#include <cuda_fp16.h>
#include <cstdint>

// DynamicPointConvBackBone via mma.sync (base-ISA HMMA; tcgen05 unavailable on
// the harness's compute_103 PTX target).
// Resample-first: only B*K rows computed. GEMM [8192 x 1728] @ [1728 x 128]
// in SINGLE-PASS fp16 (W pre-scaled by 2^14 to stay in fp16 normal range,
// accumulators unscaled by 2^-14 before LayerNorm), fp32 accumulate.
// Then LayerNorm(eps=1e-3)+ReLU epilogue, plus coords output.
// voxel_idx is int32 on the wire.

#define TILE_M 64
#define NTH    512
#define IDXP   28
#define MAXCH  28
#define CHUNK  64        // = Cin
#define ATB    8192      // A tile bytes (64 rows x 64 fp16 x 2B)
#define BTB    16384     // B tile bytes (64 k x 128 n x 2B)
#define WSCALE 16384.0f
#define WINV   (1.0f / 16384.0f)

// dynamic smem layout
#define SM_A   0
#define SM_B   (SM_A + 2 * ATB)              // 16384
#define SM_IDX (SM_B + 2 * BTB)              // 49152
#define SM_SRC (SM_IDX + TILE_M * IDXP * 4)  // 56320
#define SM_VAL (SM_SRC + TILE_M * 4)         // 56576
#define SM_RED (SM_VAL + 64)                 // 56640 (64 rows x 4 nwarps x 2)
#define SM_GB  (SM_RED + TILE_M * 8 * 4)     // 58688 (gamma 128 + beta 128)
#define SM_TOTAL (SM_GB + 256 * 4)           // 59712

__device__ __align__(16) __half g_w[MAXCH * CHUNK * 128];   // [k][n] fp16, x2^14

static __device__ __forceinline__ uint32_t smem_u32(const void* p) {
    uint32_t a;
    asm("{ .reg .u64 t; cvta.to.shared.u64 t, %1; cvt.u32.u64 %0, t; }" : "=r"(a) : "l"(p));
    return a;
}
static __device__ __forceinline__ uint32_t pack_h2(float lo, float hi) {
    uint32_t r;
    asm("cvt.rn.f16x2.f32 %0, %1, %2;" : "=r"(r) : "f"(hi), "f"(lo));
    return r;
}
static __device__ __forceinline__ void cpasync16(uint32_t dst, const void* src) {
    asm volatile("cp.async.cg.shared.global [%0], [%1], 16;" :: "r"(dst), "l"(src) : "memory");
}
static __device__ __forceinline__ void cpwait_all() {
    asm volatile("cp.async.wait_all;" ::: "memory");
}
static __device__ __forceinline__ void ldsm4(uint32_t* r, uint32_t addr) {
    asm volatile("ldmatrix.sync.aligned.m8n8.x4.shared.b16 {%0,%1,%2,%3}, [%4];"
                 : "=r"(r[0]), "=r"(r[1]), "=r"(r[2]), "=r"(r[3]) : "r"(addr));
}
static __device__ __forceinline__ void ldsm4t(uint32_t* r, uint32_t addr) {
    asm volatile("ldmatrix.sync.aligned.m8n8.x4.trans.shared.b16 {%0,%1,%2,%3}, [%4];"
                 : "=r"(r[0]), "=r"(r[1]), "=r"(r[2]), "=r"(r[3]) : "r"(addr));
}
static __device__ __forceinline__ void mma16816(float* d, const uint32_t* a,
                                                uint32_t b0, uint32_t b1) {
    asm volatile(
        "mma.sync.aligned.m16n8k16.row.col.f32.f16.f16.f32 "
        "{%0,%1,%2,%3}, {%4,%5,%6,%7}, {%8,%9}, {%0,%1,%2,%3};"
        : "+f"(d[0]), "+f"(d[1]), "+f"(d[2]), "+f"(d[3])
        : "r"(a[0]), "r"(a[1]), "r"(a[2]), "r"(a[3]), "r"(b0), "r"(b1));
}

// ---------------- prep: W -> fp16 scaled by 2^14, [k][n] ----------------
__global__ void prep_w(const float* __restrict__ W, int total) {
    int idx = blockIdx.x * blockDim.x + threadIdx.x;
    if (idx >= total) return;
    g_w[idx] = __float2half(W[idx] * WSCALE);
}

// ---------------- main fused kernel ----------------
__global__ __launch_bounds__(NTH, 1)
void fused_mma_kernel(
    const float* __restrict__ feat,   // [N, 64]
    const float* __restrict__ coors,  // [M, 3]
    const int*   __restrict__ vidx,   // [M, K3]
    const int*   __restrict__ nums,   // [B]
    const float* __restrict__ gamma,  // [128]
    const float* __restrict__ beta,   // [128]
    float* __restrict__ out_feat,     // [rows_total, 128]
    float* __restrict__ out_coor,     // [rows_total, 4]
    int N, int M, int K3, int B, int K, int rows_total)
{
    extern __shared__ __align__(128) char sm[];
    const uint32_t smb = smem_u32(sm);
    const int tid  = threadIdx.x;
    const int wid  = tid >> 5;
    const int lane = tid & 31;
    const int row0 = blockIdx.x * TILE_M;

    int* s_idx = (int*)(sm + SM_IDX);
    int* s_src = (int*)(sm + SM_SRC);
    unsigned char* s_val = (unsigned char*)(sm + SM_VAL);
    float* s_red = (float*)(sm + SM_RED);
    float* s_gb  = (float*)(sm + SM_GB);

    // per-row source & validity; gamma/beta preload
    if (tid < TILE_M) {
        int r = row0 + tid;
        int src = 0; bool valid = false;
        if (r < rows_total) {
            int b = r / K;
            int j = r - b * K;
            int off = 0;
            for (int i = 0; i < b; ++i) off += nums[i];
            valid = j < min(nums[b], K);
            src   = max(0, min(off + j, M - 1));
        }
        s_src[tid] = src;
        s_val[tid] = valid ? 1 : 0;
    }
    if (tid >= 128 && tid < 256) {
        s_gb[tid - 128] = gamma[tid - 128];
        s_gb[tid]       = beta[tid - 128];
    }
    __syncthreads();

    // neighbor indices for this row tile
    for (int i = tid; i < TILE_M * K3; i += NTH) {
        int rr = i / K3, cc = i - rr * K3;
        int v = vidx[(long long)s_src[rr] * K3 + cc];
        s_idx[rr * IDXP + cc] = (v < 0) ? -1 : min(v, N - 1);
    }
    __syncthreads();

    // -------- loader helpers --------
    const int arow = tid >> 3;          // gather row 0..63
    const int aseg = tid & 7;           // 32B segment of 256B fp32 feature row
    float4 pa0, pa1;

    auto a_issue = [&](int c) {
        int gi = s_idx[arow * IDXP + c];
        if (gi >= 0) {
            const float4* src = (const float4*)(feat + (size_t)gi * CHUNK) + aseg * 2;
            pa0 = __ldg(src + 0);
            pa1 = __ldg(src + 1);
        } else {
            pa0 = pa1 = make_float4(0.f, 0.f, 0.f, 0.f);
        }
    };
    auto a_store = [&](int buf) {
        uint4 h;
        h.x = pack_h2(pa0.x, pa0.y);
        h.y = pack_h2(pa0.z, pa0.w);
        h.z = pack_h2(pa1.x, pa1.y);
        h.w = pack_h2(pa1.z, pa1.w);
        const int o = arow * 128 + ((aseg ^ (arow & 7)) << 4);
        *(uint4*)(sm + SM_A + buf * ATB + o) = h;
    };
    auto b_issue = [&](int c, int buf) {
        const char* srcB = (const char*)g_w + (size_t)c * BTB;
        uint32_t dB = smb + SM_B + buf * BTB;
        #pragma unroll
        for (int j = 0; j < 2; ++j) {
            int idx  = tid + j * NTH;
            int krow = idx >> 4;
            int col  = idx & 15;
            int dof  = krow * 256 + ((col ^ (krow & 7)) << 4);
            int so   = krow * 256 + col * 16;
            cpasync16(dB + dof, srcB + so);
        }
    };

    // -------- compute (per warp: m16 x n32, single pass) --------
    const int mw = wid & 3, nw = wid >> 2;
    const int m0 = mw * 16;
    float acc[4][4];
    #pragma unroll
    for (int t = 0; t < 4; ++t)
        #pragma unroll
        for (int q = 0; q < 4; ++q) acc[t][q] = 0.f;

    const int a_r  = m0 + (lane & 15);
    const int a_hi = (lane >> 4);
    const int k_l  = (lane & 15);

    auto mma_chunk = [&](int buf) {
        const uint32_t aB = smb + SM_A + buf * ATB + a_r * 128;
        const uint32_t bB = smb + SM_B + buf * BTB;
        const int asw = (a_r & 7);
        #pragma unroll
        for (int ks = 0; ks < 4; ++ks) {
            uint32_t ah[4];
            const int acol = ks * 2 + a_hi;
            ldsm4(ah, aB + (uint32_t)((acol ^ asw) << 4));
            const int krow = ks * 16 + k_l;
            const uint32_t brow = (uint32_t)(krow * 256);
            const int ksw = (krow & 7);
            #pragma unroll
            for (int tt = 0; tt < 2; ++tt) {
                uint32_t bh[4];
                const int bcol = nw * 4 + tt * 2 + a_hi;
                ldsm4t(bh, brow + bB + (uint32_t)((bcol ^ ksw) << 4));
                mma16816(acc[2 * tt],     ah, bh[0], bh[1]);
                mma16816(acc[2 * tt + 1], ah, bh[2], bh[3]);
            }
        }
    };

    // -------- pipelined main loop --------
    b_issue(0, 0);
    a_issue(0);
    a_store(0);
    cpwait_all();
    __syncthreads();

    for (int c = 0; c < K3; ++c) {
        const int buf = c & 1;
        const bool nxt = (c + 1) < K3;
        if (nxt) { b_issue(c + 1, buf ^ 1); a_issue(c + 1); }
        mma_chunk(buf);
        if (nxt) a_store(buf ^ 1);
        cpwait_all();
        __syncthreads();
    }

    // -------- unscale (W was x2^14) --------
    #pragma unroll
    for (int t = 0; t < 4; ++t)
        #pragma unroll
        for (int q = 0; q < 4; ++q) acc[t][q] *= WINV;

    // -------- LayerNorm epilogue --------
    // thread rows r0 = m0+(lane>>2), r1 = r0+8
    // tile t = tt*2+j: cols = nw*32 + tt*16 + j*8 + (lane&3)*2
    {
        float s0 = 0.f, q0 = 0.f, s1 = 0.f, q1 = 0.f;
        #pragma unroll
        for (int t = 0; t < 4; ++t) {
            s0 += acc[t][0] + acc[t][1];
            q0 += acc[t][0] * acc[t][0] + acc[t][1] * acc[t][1];
            s1 += acc[t][2] + acc[t][3];
            q1 += acc[t][2] * acc[t][2] + acc[t][3] * acc[t][3];
        }
        #pragma unroll
        for (int m = 1; m <= 2; m <<= 1) {
            s0 += __shfl_xor_sync(0xffffffffu, s0, m);
            q0 += __shfl_xor_sync(0xffffffffu, q0, m);
            s1 += __shfl_xor_sync(0xffffffffu, s1, m);
            q1 += __shfl_xor_sync(0xffffffffu, q1, m);
        }
        if ((lane & 3) == 0) {
            int r0 = m0 + (lane >> 2);
            s_red[r0 * 8 + nw * 2 + 0] = s0;
            s_red[r0 * 8 + nw * 2 + 1] = q0;
            s_red[(r0 + 8) * 8 + nw * 2 + 0] = s1;
            s_red[(r0 + 8) * 8 + nw * 2 + 1] = q1;
        }
    }
    __syncthreads();

    {
        const int r0 = m0 + (lane >> 2);
        const int r1 = r0 + 8;
        const float invC = 1.0f / 128.0f;
        float sA = s_red[r0 * 8 + 0] + s_red[r0 * 8 + 2] + s_red[r0 * 8 + 4] + s_red[r0 * 8 + 6];
        float qA = s_red[r0 * 8 + 1] + s_red[r0 * 8 + 3] + s_red[r0 * 8 + 5] + s_red[r0 * 8 + 7];
        float sB = s_red[r1 * 8 + 0] + s_red[r1 * 8 + 2] + s_red[r1 * 8 + 4] + s_red[r1 * 8 + 6];
        float qB = s_red[r1 * 8 + 1] + s_red[r1 * 8 + 3] + s_red[r1 * 8 + 5] + s_red[r1 * 8 + 7];
        float muA = sA * invC, muB = sB * invC;
        float ivA = rsqrtf(fmaxf(qA * invC - muA * muA, 0.f) + 1e-3f);
        float ivB = rsqrtf(fmaxf(qB * invC - muB * muB, 0.f) + 1e-3f);
        const int gr0 = row0 + r0, gr1 = row0 + r1;
        const bool vA = (gr0 < rows_total) && s_val[r0];
        const bool vB = (gr1 < rows_total) && s_val[r1];
        #pragma unroll
        for (int t = 0; t < 4; ++t) {
            const int c = nw * 32 + (t >> 1) * 16 + (t & 1) * 8 + (lane & 3) * 2;
            const float g0 = s_gb[c], g1 = s_gb[c + 1];
            const float b0 = s_gb[128 + c], b1 = s_gb[128 + c + 1];
            if (gr0 < rows_total) {
                float2 o = make_float2(0.f, 0.f);
                if (vA) {
                    o.x = fmaxf((acc[t][0] - muA) * ivA * g0 + b0, 0.f);
                    o.y = fmaxf((acc[t][1] - muA) * ivA * g1 + b1, 0.f);
                }
                *(float2*)(out_feat + (size_t)gr0 * 128 + c) = o;
            }
            if (gr1 < rows_total) {
                float2 o = make_float2(0.f, 0.f);
                if (vB) {
                    o.x = fmaxf((acc[t][2] - muB) * ivB * g0 + b0, 0.f);
                    o.y = fmaxf((acc[t][3] - muB) * ivB * g1 + b1, 0.f);
                }
                *(float2*)(out_feat + (size_t)gr1 * 128 + c) = o;
            }
        }
    }

    // -------- coords --------
    if (tid < TILE_M) {
        int r = row0 + tid;
        if (r < rows_total) {
            int b = r / K;
            float col0 = (b < B - 1) ? (float)(b + 1) : 0.f;
            float x = 0.f, y = 0.f, z = 0.f;
            if (s_val[tid]) {
                int src = s_src[tid];
                x = coors[src * 3 + 0];
                y = coors[src * 3 + 1];
                z = coors[src * 3 + 2];
            }
            ((float4*)out_coor)[r] = make_float4(col0, x, y, z);
        }
    }
}

extern "C" void kernel_launch(void* const* d_in, const int* in_sizes, int n_in,
                              void* d_out, int out_size) {
    const float* feat     = (const float*)d_in[0];
    const float* coors    = (const float*)d_in[1];
    const int*   vidx     = (const int*)d_in[2];
    const int*   num_list = (const int*)d_in[3];
    const float* W        = (const float*)d_in[4];
    const float* gamma    = (const float*)d_in[5];
    const float* beta     = (const float*)d_in[6];

    int B    = in_sizes[3];
    int Cout = in_sizes[5];                 // 128
    int M    = in_sizes[1] / 3;
    int K3   = in_sizes[2] / M;             // 27
    int Cin  = (in_sizes[4] / Cout) / K3;   // 64
    int N    = in_sizes[0] / Cin;
    int Ktot = K3 * Cin;

    int rows_total = out_size / (Cout + 4); // B*K
    int K = rows_total / B;

    float* out_feat = (float*)d_out;
    float* out_coor = out_feat + (size_t)rows_total * Cout;

    prep_w<<<(Ktot * Cout + 255) / 256, 256>>>(W, Ktot * Cout);

    cudaFuncSetAttribute(fused_mma_kernel,
                         cudaFuncAttributeMaxDynamicSharedMemorySize, SM_TOTAL);
    int grid = (rows_total + TILE_M - 1) / TILE_M;
    fused_mma_kernel<<<grid, NTH, SM_TOTAL>>>(feat, coors, vidx, num_list, gamma, beta,
                                              out_feat, out_coor,
                                              N, M, K3, B, K, rows_total);
}

// round 11
// speedup vs baseline: 7.4818x; 1.0156x over previous
#include <cuda_runtime.h>
#include <cuda_fp16.h>
#include <cstdint>

// DynamicPointConvBackBone via mma.sync (base-ISA HMMA; tcgen05 unavailable on
// the harness's compute_103 PTX target).
// Resample-first: only B*K rows computed. GEMM [8192 x 1728] @ [1728 x 128]
// in single-pass fp16 (W pre-scaled by 2^14; accumulators unscaled before LN),
// fp32 accumulate. LayerNorm(eps=1e-3)+ReLU epilogue + coords output.
// R8: TILE_M=32 / 256 threads / grid=256 -> 2 CTAs per SM so barrier and
// load-latency bubbles of one CTA are hidden under the other CTA's HMMA.

#define TILE_M 32
#define NTH    256
#define IDXP   28
#define MAXCH  28
#define CHUNK  64        // = Cin
#define ATB    4096      // A tile bytes (32 rows x 64 fp16 x 2B)
#define BTB    16384     // B tile bytes (64 k x 128 n x 2B)
#define WSCALE 16384.0f
#define WINV   (1.0f / 16384.0f)

// dynamic smem layout
#define SM_A   0
#define SM_B   (SM_A + 2 * ATB)              // 8192
#define SM_IDX (SM_B + 2 * BTB)              // 40960
#define SM_SRC (SM_IDX + TILE_M * IDXP * 4)  // 44544
#define SM_VAL (SM_SRC + TILE_M * 4)         // 44672
#define SM_RED (SM_VAL + 32)                 // 44704 (32 rows x 4 nwarps x 2)
#define SM_GB  (SM_RED + TILE_M * 8 * 4)     // 45728 (gamma 128 + beta 128)
#define SM_TOTAL (SM_GB + 256 * 4)           // 46752

__device__ __align__(16) __half g_w[MAXCH * CHUNK * 128];   // [k][n] fp16, x2^14

static __device__ __forceinline__ uint32_t smem_u32(const void* p) {
    uint32_t a;
    asm("{ .reg .u64 t; cvta.to.shared.u64 t, %1; cvt.u32.u64 %0, t; }" : "=r"(a) : "l"(p));
    return a;
}
static __device__ __forceinline__ uint32_t pack_h2(float lo, float hi) {
    uint32_t r;
    asm("cvt.rn.f16x2.f32 %0, %1, %2;" : "=r"(r) : "f"(hi), "f"(lo));
    return r;
}
static __device__ __forceinline__ void cpasync16(uint32_t dst, const void* src) {
    asm volatile("cp.async.cg.shared.global [%0], [%1], 16;" :: "r"(dst), "l"(src) : "memory");
}
static __device__ __forceinline__ void cpwait_all() {
    asm volatile("cp.async.wait_all;" ::: "memory");
}
static __device__ __forceinline__ void ldsm4(uint32_t* r, uint32_t addr) {
    asm volatile("ldmatrix.sync.aligned.m8n8.x4.shared.b16 {%0,%1,%2,%3}, [%4];"
                 : "=r"(r[0]), "=r"(r[1]), "=r"(r[2]), "=r"(r[3]) : "r"(addr));
}
static __device__ __forceinline__ void ldsm4t(uint32_t* r, uint32_t addr) {
    asm volatile("ldmatrix.sync.aligned.m8n8.x4.trans.shared.b16 {%0,%1,%2,%3}, [%4];"
                 : "=r"(r[0]), "=r"(r[1]), "=r"(r[2]), "=r"(r[3]) : "r"(addr));
}
static __device__ __forceinline__ void mma16816(float* d, const uint32_t* a,
                                                uint32_t b0, uint32_t b1) {
    asm volatile(
        "mma.sync.aligned.m16n8k16.row.col.f32.f16.f16.f32 "
        "{%0,%1,%2,%3}, {%4,%5,%6,%7}, {%8,%9}, {%0,%1,%2,%3};"
        : "+f"(d[0]), "+f"(d[1]), "+f"(d[2]), "+f"(d[3])
        : "r"(a[0]), "r"(a[1]), "r"(a[2]), "r"(a[3]), "r"(b0), "r"(b1));
}

// ---------------- prep: W -> fp16 scaled by 2^14, [k][n] ----------------
__global__ void prep_w(const float* __restrict__ W, int total) {
    int idx = blockIdx.x * blockDim.x + threadIdx.x;
    if (idx >= total) return;
    g_w[idx] = __float2half(W[idx] * WSCALE);
}

// ---------------- main fused kernel ----------------
__global__ __launch_bounds__(NTH, 2)
void fused_mma_kernel(
    const float* __restrict__ feat,   // [N, 64]
    const float* __restrict__ coors,  // [M, 3]
    const int*   __restrict__ vidx,   // [M, K3]
    const int*   __restrict__ nums,   // [B]
    const float* __restrict__ gamma,  // [128]
    const float* __restrict__ beta,   // [128]
    float* __restrict__ out_feat,     // [rows_total, 128]
    float* __restrict__ out_coor,     // [rows_total, 4]
    int N, int M, int K3, int B, int K, int rows_total)
{
    extern __shared__ __align__(128) char sm[];
    const uint32_t smb = smem_u32(sm);
    const int tid  = threadIdx.x;
    const int wid  = tid >> 5;
    const int lane = tid & 31;
    const int row0 = blockIdx.x * TILE_M;

    int* s_idx = (int*)(sm + SM_IDX);
    int* s_src = (int*)(sm + SM_SRC);
    unsigned char* s_val = (unsigned char*)(sm + SM_VAL);
    float* s_red = (float*)(sm + SM_RED);
    float* s_gb  = (float*)(sm + SM_GB);

    // per-row source & validity
    if (tid < TILE_M) {
        int r = row0 + tid;
        int src = 0; bool valid = false;
        if (r < rows_total) {
            int b = r / K;
            int j = r - b * K;
            int off = 0;
            for (int i = 0; i < b; ++i) off += nums[i];
            valid = j < min(nums[b], K);
            src   = max(0, min(off + j, M - 1));
        }
        s_src[tid] = src;
        s_val[tid] = valid ? 1 : 0;
    }
    if (tid >= 128) {
        s_gb[tid - 128] = gamma[tid - 128];
        s_gb[tid]       = beta[tid - 128];
    }
    __syncthreads();

    // neighbor indices for this row tile
    for (int i = tid; i < TILE_M * K3; i += NTH) {
        int rr = i / K3, cc = i - rr * K3;
        int v = vidx[(long long)s_src[rr] * K3 + cc];
        s_idx[rr * IDXP + cc] = (v < 0) ? -1 : min(v, N - 1);
    }
    __syncthreads();

    // -------- loader helpers --------
    const int arow = tid >> 3;          // gather row 0..31
    const int aseg = tid & 7;           // 32B segment of 256B fp32 feature row
    float4 pa0, pa1;

    auto a_issue = [&](int c) {
        int gi = s_idx[arow * IDXP + c];
        if (gi >= 0) {
            const float4* src = (const float4*)(feat + (size_t)gi * CHUNK) + aseg * 2;
            pa0 = __ldg(src + 0);
            pa1 = __ldg(src + 1);
        } else {
            pa0 = pa1 = make_float4(0.f, 0.f, 0.f, 0.f);
        }
    };
    auto a_store = [&](int buf) {
        uint4 h;
        h.x = pack_h2(pa0.x, pa0.y);
        h.y = pack_h2(pa0.z, pa0.w);
        h.z = pack_h2(pa1.x, pa1.y);
        h.w = pack_h2(pa1.z, pa1.w);
        const int o = arow * 128 + ((aseg ^ (arow & 7)) << 4);
        *(uint4*)(sm + SM_A + buf * ATB + o) = h;
    };
    auto b_issue = [&](int c, int buf) {
        const char* srcB = (const char*)g_w + (size_t)c * BTB;
        uint32_t dB = smb + SM_B + buf * BTB;
        #pragma unroll
        for (int j = 0; j < 4; ++j) {
            int idx  = tid + j * NTH;
            int krow = idx >> 4;
            int col  = idx & 15;
            int dof  = krow * 256 + ((col ^ (krow & 7)) << 4);
            int so   = krow * 256 + col * 16;
            cpasync16(dB + dof, srcB + so);
        }
    };

    // -------- compute (per warp: m16 x n32) --------
    const int mw = wid & 1, nw = wid >> 1;   // 2 m-warps x 4 n-warps
    const int m0 = mw * 16;
    float acc[4][4];
    #pragma unroll
    for (int t = 0; t < 4; ++t)
        #pragma unroll
        for (int q = 0; q < 4; ++q) acc[t][q] = 0.f;

    const int a_r  = m0 + (lane & 15);
    const int a_hi = (lane >> 4);
    const int k_l  = (lane & 15);

    auto mma_chunk = [&](int buf) {
        const uint32_t aB = smb + SM_A + buf * ATB + a_r * 128;
        const uint32_t bB = smb + SM_B + buf * BTB;
        const int asw = (a_r & 7);
        #pragma unroll
        for (int ks = 0; ks < 4; ++ks) {
            uint32_t ah[4];
            const int acol = ks * 2 + a_hi;
            ldsm4(ah, aB + (uint32_t)((acol ^ asw) << 4));
            const int krow = ks * 16 + k_l;
            const uint32_t brow = (uint32_t)(krow * 256);
            const int ksw = (krow & 7);
            #pragma unroll
            for (int tt = 0; tt < 2; ++tt) {
                uint32_t bh[4];
                const int bcol = nw * 4 + tt * 2 + a_hi;
                ldsm4t(bh, brow + bB + (uint32_t)((bcol ^ ksw) << 4));
                mma16816(acc[2 * tt],     ah, bh[0], bh[1]);
                mma16816(acc[2 * tt + 1], ah, bh[2], bh[3]);
            }
        }
    };

    // -------- pipelined main loop --------
    b_issue(0, 0);
    a_issue(0);
    a_store(0);
    cpwait_all();
    __syncthreads();

    for (int c = 0; c < K3; ++c) {
        const int buf = c & 1;
        const bool nxt = (c + 1) < K3;
        if (nxt) { b_issue(c + 1, buf ^ 1); a_issue(c + 1); }
        mma_chunk(buf);
        if (nxt) a_store(buf ^ 1);
        cpwait_all();
        __syncthreads();
    }

    // -------- unscale (W was x2^14) --------
    #pragma unroll
    for (int t = 0; t < 4; ++t)
        #pragma unroll
        for (int q = 0; q < 4; ++q) acc[t][q] *= WINV;

    // -------- LayerNorm epilogue --------
    {
        float s0 = 0.f, q0 = 0.f, s1 = 0.f, q1 = 0.f;
        #pragma unroll
        for (int t = 0; t < 4; ++t) {
            s0 += acc[t][0] + acc[t][1];
            q0 += acc[t][0] * acc[t][0] + acc[t][1] * acc[t][1];
            s1 += acc[t][2] + acc[t][3];
            q1 += acc[t][2] * acc[t][2] + acc[t][3] * acc[t][3];
        }
        #pragma unroll
        for (int m = 1; m <= 2; m <<= 1) {
            s0 += __shfl_xor_sync(0xffffffffu, s0, m);
            q0 += __shfl_xor_sync(0xffffffffu, q0, m);
            s1 += __shfl_xor_sync(0xffffffffu, s1, m);
            q1 += __shfl_xor_sync(0xffffffffu, q1, m);
        }
        if ((lane & 3) == 0) {
            int r0 = m0 + (lane >> 2);
            s_red[r0 * 8 + nw * 2 + 0] = s0;
            s_red[r0 * 8 + nw * 2 + 1] = q0;
            s_red[(r0 + 8) * 8 + nw * 2 + 0] = s1;
            s_red[(r0 + 8) * 8 + nw * 2 + 1] = q1;
        }
    }
    __syncthreads();

    {
        const int r0 = m0 + (lane >> 2);
        const int r1 = r0 + 8;
        const float invC = 1.0f / 128.0f;
        float sA = s_red[r0 * 8 + 0] + s_red[r0 * 8 + 2] + s_red[r0 * 8 + 4] + s_red[r0 * 8 + 6];
        float qA = s_red[r0 * 8 + 1] + s_red[r0 * 8 + 3] + s_red[r0 * 8 + 5] + s_red[r0 * 8 + 7];
        float sB = s_red[r1 * 8 + 0] + s_red[r1 * 8 + 2] + s_red[r1 * 8 + 4] + s_red[r1 * 8 + 6];
        float qB = s_red[r1 * 8 + 1] + s_red[r1 * 8 + 3] + s_red[r1 * 8 + 5] + s_red[r1 * 8 + 7];
        float muA = sA * invC, muB = sB * invC;
        float ivA = rsqrtf(fmaxf(qA * invC - muA * muA, 0.f) + 1e-3f);
        float ivB = rsqrtf(fmaxf(qB * invC - muB * muB, 0.f) + 1e-3f);
        const int gr0 = row0 + r0, gr1 = row0 + r1;
        const bool vA = (gr0 < rows_total) && s_val[r0];
        const bool vB = (gr1 < rows_total) && s_val[r1];
        #pragma unroll
        for (int t = 0; t < 4; ++t) {
            const int c = nw * 32 + (t >> 1) * 16 + (t & 1) * 8 + (lane & 3) * 2;
            const float g0 = s_gb[c], g1 = s_gb[c + 1];
            const float b0 = s_gb[128 + c], b1 = s_gb[128 + c + 1];
            if (gr0 < rows_total) {
                float2 o = make_float2(0.f, 0.f);
                if (vA) {
                    o.x = fmaxf((acc[t][0] - muA) * ivA * g0 + b0, 0.f);
                    o.y = fmaxf((acc[t][1] - muA) * ivA * g1 + b1, 0.f);
                }
                *(float2*)(out_feat + (size_t)gr0 * 128 + c) = o;
            }
            if (gr1 < rows_total) {
                float2 o = make_float2(0.f, 0.f);
                if (vB) {
                    o.x = fmaxf((acc[t][2] - muB) * ivB * g0 + b0, 0.f);
                    o.y = fmaxf((acc[t][3] - muB) * ivB * g1 + b1, 0.f);
                }
                *(float2*)(out_feat + (size_t)gr1 * 128 + c) = o;
            }
        }
    }

    // -------- coords --------
    if (tid < TILE_M) {
        int r = row0 + tid;
        if (r < rows_total) {
            int b = r / K;
            float col0 = (b < B - 1) ? (float)(b + 1) : 0.f;
            float x = 0.f, y = 0.f, z = 0.f;
            if (s_val[tid]) {
                int src = s_src[tid];
                x = coors[src * 3 + 0];
                y = coors[src * 3 + 1];
                z = coors[src * 3 + 2];
            }
            ((float4*)out_coor)[r] = make_float4(col0, x, y, z);
        }
    }
}

extern "C" void kernel_launch(void* const* d_in, const int* in_sizes, int n_in,
                              void* d_out, int out_size) {
    const float* feat     = (const float*)d_in[0];
    const float* coors    = (const float*)d_in[1];
    const int*   vidx     = (const int*)d_in[2];
    const int*   num_list = (const int*)d_in[3];
    const float* W        = (const float*)d_in[4];
    const float* gamma    = (const float*)d_in[5];
    const float* beta     = (const float*)d_in[6];

    int B    = in_sizes[3];
    int Cout = in_sizes[5];                 // 128
    int M    = in_sizes[1] / 3;
    int K3   = in_sizes[2] / M;             // 27
    int Cin  = (in_sizes[4] / Cout) / K3;   // 64
    int N    = in_sizes[0] / Cin;
    int Ktot = K3 * Cin;

    int rows_total = out_size / (Cout + 4); // B*K
    int K = rows_total / B;

    float* out_feat = (float*)d_out;
    float* out_coor = out_feat + (size_t)rows_total * Cout;

    prep_w<<<(Ktot * Cout + 255) / 256, 256>>>(W, Ktot * Cout);

    cudaFuncSetAttribute(fused_mma_kernel,
                         cudaFuncAttributeMaxDynamicSharedMemorySize, SM_TOTAL);
    int grid = (rows_total + TILE_M - 1) / TILE_M;
    fused_mma_kernel<<<grid, NTH, SM_TOTAL>>>(feat, coors, vidx, num_list, gamma, beta,
                                              out_feat, out_coor,
                                              N, M, K3, B, K, rows_total);
}